// round 13
// baseline (speedup 1.0000x reference)
#include <cuda_runtime.h>
#include <cuda_bf16.h>
#include <cstdint>

// DCNv2 forward. BOTH convs on tensor cores (mma.sync m16n8k16 bf16 hi/lo
// split). om conv = regular-im2col GEMM; main = deformable-gather GEMM.
// R13: main CTA = 1 row (64 px) x 256 oc, smem 113.5KB -> 2 CTAs/SM.

typedef unsigned int uint;
typedef unsigned short ushort;

#define BB     8
#define CIN    256
#define COUT   256
#define HW     64
#define KKN    9
#define KTOT   2304
#define CHUNKS 72            // K chunks of 32 (2 k16 steps each)

// ---------------- device scratch (static: allocation-free) ----------------
// g_om layout: [grp(0=dy,1=dx,2=sig(mask))][b][k][y][x]  (bias+sigmoid done)
__device__ float g_om[3 * BB * KKN * HW * HW];
__device__ __align__(16) __nv_bfloat16 g_wbh[CHUNKS * COUT * 32];
__device__ __align__(16) __nv_bfloat16 g_wbl[CHUNKS * COUT * 32];
__device__ __align__(16) __nv_bfloat16 g_wobh[CHUNKS * 32 * 32];
__device__ __align__(16) __nv_bfloat16 g_wobl[CHUNKS * 32 * 32];

__device__ __forceinline__ uint smem_u32(const void* p) {
    uint a;
    asm("{ .reg .u64 t; cvta.to.shared.u64 t, %1; cvt.u32.u64 %0, t; }"
        : "=r"(a) : "l"(p));
    return a;
}

#define LDM_X4(r, addr) \
    asm volatile("ldmatrix.sync.aligned.m8n8.x4.shared.b16 {%0,%1,%2,%3}, [%4];" \
        : "=r"((r)[0]), "=r"((r)[1]), "=r"((r)[2]), "=r"((r)[3]) : "r"(addr))

#define MMA16816(d, a, b) \
    asm volatile("mma.sync.aligned.m16n8k16.row.col.f32.bf16.bf16.f32 " \
        "{%0,%1,%2,%3},{%4,%5,%6,%7},{%8,%9},{%0,%1,%2,%3};" \
        : "+f"((d)[0]), "+f"((d)[1]), "+f"((d)[2]), "+f"((d)[3]) \
        : "r"((a)[0]), "r"((a)[1]), "r"((a)[2]), "r"((a)[3]), \
          "r"((b)[0]), "r"((b)[1]))

// ---------------------------------------------------------------------------
// Kernel P1: dense bf16-split main weights, chunk-major [t][oc][32].
// ---------------------------------------------------------------------------
__global__ void prep_w_kernel(const float* __restrict__ w_dcn) {
    int i = blockIdx.x * 256 + threadIdx.x;
    int kkl = i & 31;
    int oc  = (i >> 5) & 255;
    int t   = i >> 13;
    int kk  = t * 32 + kkl;
    int c   = kk / 9;
    int k   = kk - c * 9;
    float w = w_dcn[(oc * CIN + c) * KKN + k];
    __nv_bfloat16 h = __float2bfloat16(w);
    g_wbh[i] = h;
    g_wbl[i] = __float2bfloat16(w - __bfloat162float(h));
}

// ---------------------------------------------------------------------------
// Kernel P2: om weights, padded to 32 oc, chunk-major [t][oc32][32].
// ---------------------------------------------------------------------------
__global__ void prep_wo_kernel(const float* __restrict__ w_om) {
    int i = blockIdx.x * 256 + threadIdx.x;
    int kkl = i & 31;
    int oc  = (i >> 5) & 31;
    int t   = i >> 10;
    int kk  = t * 32 + kkl;
    int c   = kk / 9;
    int k   = kk - c * 9;
    float w = (oc < 27) ? w_om[(oc * CIN + c) * KKN + k] : 0.f;
    __nv_bfloat16 h = __float2bfloat16(w);
    g_wobh[i] = h;
    g_wobl[i] = __float2bfloat16(w - __bfloat162float(h));
}

// ---------------------------------------------------------------------------
// Kernel A (om2): offset/mask conv as mma GEMM (verified R12 form).
// ---------------------------------------------------------------------------
#define A2BYTES 20480
#define B2BYTES 2560
#define STGB2   46080
#define SM2_TOTAL (2 * STGB2)

__device__ __forceinline__ void stage_om(
    char* smem, int bufoff, int t, int b, int y0, int tid,
    const float* __restrict__ input) {
    if (tid < 64) {
        int oc = tid & 31;
        const __nv_bfloat16* srcp = (tid < 32) ? g_wobh : g_wobl;
        const uint4* src = (const uint4*)(srcp + ((size_t)t * 32 + oc) * 32);
        char* dst = smem + bufoff + 2 * A2BYTES + ((tid >= 32) ? B2BYTES : 0) + oc * 80;
#pragma unroll
        for (int q = 0; q < 4; ++q)
            *(uint4*)(dst + q * 16) = src[q];
    }
    const int px = tid & 255;
    const int kg = tid >> 8;
    const int x  = px & 63;
    const int y  = y0 + (px >> 6);
    const int kks = t * 32 + kg * 16;
    int c = kks / 9;
    int k = kks - c * 9;
    const float* pl = input + (((size_t)b * CIN + c) << 12);
    uint hi[8], lo[8];
#pragma unroll
    for (int i = 0; i < 16; ++i) {
        int ki = k / 3, kj = k - ki * 3;
        int yy = y - 1 + ki, xx = x - 1 + kj;
        float v = 0.f;
        if (yy >= 0 && yy < HW && xx >= 0 && xx < HW)
            v = __ldg(pl + yy * HW + xx);
        __nv_bfloat16 h = __float2bfloat16(v);
        __nv_bfloat16 l = __float2bfloat16(v - __bfloat162float(h));
        uint hu = (uint)__bfloat16_as_ushort(h);
        uint lu = (uint)__bfloat16_as_ushort(l);
        if (i & 1) { hi[i >> 1] |= hu << 16; lo[i >> 1] |= lu << 16; }
        else       { hi[i >> 1]  = hu;       lo[i >> 1]  = lu; }
        if (++k == 9) { k = 0; pl += HW * HW; }
    }
    char* Ah = smem + bufoff + px * 80 + kg * 32;
#pragma unroll
    for (int q = 0; q < 2; ++q) {
        *(uint4*)(Ah + q * 16)           = make_uint4(hi[q*4], hi[q*4+1], hi[q*4+2], hi[q*4+3]);
        *(uint4*)(Ah + A2BYTES + q * 16) = make_uint4(lo[q*4], lo[q*4+1], lo[q*4+2], lo[q*4+3]);
    }
}

__global__ __launch_bounds__(512, 1) void om2_kernel(
    const float* __restrict__ input,
    const float* __restrict__ b_om) {
    extern __shared__ char smem[];
    const int tid  = threadIdx.x;
    const int wid  = tid >> 5;
    const int lane = tid & 31;
    const int y0   = blockIdx.x * 4;
    const int b    = blockIdx.y;
    const uint sbase = smem_u32(smem);

    const int mwarp = wid * 16;
    const uint aLane = (uint)((mwarp + (lane & 15)) * 80 + ((lane >> 4) & 1) * 16);
    const uint bLane = (uint)(((lane & 7) + ((lane >> 4) & 1) * 8) * 80
                              + ((lane >> 3) & 1) * 16);

    float acc[4][4];
#pragma unroll
    for (int nt = 0; nt < 4; ++nt)
#pragma unroll
        for (int q = 0; q < 4; ++q) acc[nt][q] = 0.f;

    stage_om(smem, 0, 0, b, y0, tid, input);
    __syncthreads();

#pragma unroll 1
    for (int t = 0; t < CHUNKS; ++t) {
        const int s = t & 1;
        if (t + 1 < CHUNKS)
            stage_om(smem, (s ^ 1) * STGB2, t + 1, b, y0, tid, input);

        const uint aBase = sbase + s * STGB2 + aLane;
        const uint bBase = sbase + s * STGB2 + 2 * A2BYTES + bLane;
#pragma unroll
        for (int ks = 0; ks < 2; ++ks) {
            uint ah[4], al[4];
            LDM_X4(ah, aBase + ks * 32);
            LDM_X4(al, aBase + ks * 32 + A2BYTES);
#pragma unroll
            for (int g = 0; g < 2; ++g) {
                uint bh[4], bl[4];
                uint ba = bBase + g * (16 * 80) + ks * 32;
                LDM_X4(bh, ba);
                LDM_X4(bl, ba + B2BYTES);
                MMA16816(acc[2 * g],     ah, bh);
                MMA16816(acc[2 * g],     ah, bl);
                MMA16816(acc[2 * g],     al, bh);
                MMA16816(acc[2 * g + 1], ah, bh + 2);
                MMA16816(acc[2 * g + 1], ah, bl + 2);
                MMA16816(acc[2 * g + 1], al, bh + 2);
            }
        }
        __syncthreads();
    }

    const int tq = lane >> 2, tr = lane & 3;
#pragma unroll
    for (int nt = 0; nt < 4; ++nt) {
#pragma unroll
        for (int q = 0; q < 4; ++q) {
            int oc = nt * 8 + tr * 2 + (q & 1);
            if (oc >= 27) continue;
            int px = mwarp + tq + ((q >> 1) ? 8 : 0);
            int y  = y0 + (px >> 6);
            int x  = px & 63;
            float v = acc[nt][q] + __ldg(b_om + oc);
            int grp = oc / 9;
            int k   = oc - grp * 9;
            if (grp == 2) v = 1.f / (1.f + expf(-v));
            g_om[(((size_t)grp * BB + b) * KKN + k) * (HW * HW) + y * HW + x] = v;
        }
    }
}

// ---------------------------------------------------------------------------
// Kernel B: fused bilinear sampling + mma.sync GEMM.
// R13: CTA = 1 row (64 px) x 256 oc, 512 threads, warp tile 16x64.
// smem 116224 B -> 2 CTAs/SM (occ 25%->50%); two independent barrier
// domains per SM hide staging-gather latency behind the other CTA's MMAs.
// ---------------------------------------------------------------------------
#define ABYTES 5120             // 64 rows * 80 B (one split)
#define BBYTES 20480            // 256 rows * 80 B (one split)
#define STGB   51200            // Ah | Al | Bh | Bl
#define SM_WM  0                // float4[576]
#define SM_IM  9216             // ushort4[576]
#define SM_BUF 13824
#define SM_TOTAL (SM_BUF + 2 * STGB)   // 116224

__device__ __forceinline__ void stage_chunk(
    char* smem, int bufoff, int t, int b, int tid,
    const float4* s_wm4, const ushort4* s_im4,
    const float* __restrict__ input) {
    // ---- B: (split = tid>>8, oc = tid&255), 64 B contiguous ----
    {
        const int oc = tid & 255;
        const __nv_bfloat16* srcp = (tid < 256) ? g_wbh : g_wbl;
        const uint4* src = (const uint4*)(srcp + ((size_t)t * COUT + oc) * 32);
        char* dst = smem + bufoff + 2 * ABYTES + ((tid >> 8) ? BBYTES : 0) + oc * 80;
#pragma unroll
        for (int q = 0; q < 4; ++q)
            *(uint4*)(dst + q * 16) = src[q];
    }
    // ---- A: px-major, 4 samples/thread (px = tid&63, kg = tid>>6) ----
    const int px = tid & 63;
    const int kg = tid >> 6;              // 0..7
    const int kks = t * 32 + kg * 4;
    int c = kks / 9;
    int k = kks - c * 9;
    const float* pl = input + (((size_t)b * CIN + c) << 12);
    uint hi[2], lo[2];
#pragma unroll
    for (int i = 0; i < 4; i += 2) {
        int mA = px + k * 64;
        const float* plA = pl;
        float4  wA = s_wm4[mA];
        ushort4 iA = s_im4[mA];
        if (++k == 9) { k = 0; pl += HW * HW; }
        int mB = px + k * 64;
        const float* plB = pl;
        float4  wB = s_wm4[mB];
        ushort4 iB = s_im4[mB];
        if (++k == 9) { k = 0; pl += HW * HW; }
        float a0 = __ldg(plA + iA.x), a1 = __ldg(plA + iA.y);
        float a2 = __ldg(plA + iA.z), a3 = __ldg(plA + iA.w);
        float b0 = __ldg(plB + iB.x), b1 = __ldg(plB + iB.y);
        float b2 = __ldg(plB + iB.z), b3 = __ldg(plB + iB.w);
        float vA = wA.x * a0 + wA.y * a1 + wA.z * a2 + wA.w * a3;
        float vB = wB.x * b0 + wB.y * b1 + wB.z * b2 + wB.w * b3;
        __nv_bfloat16 hA = __float2bfloat16(vA);
        __nv_bfloat16 lA = __float2bfloat16(vA - __bfloat162float(hA));
        __nv_bfloat16 hB = __float2bfloat16(vB);
        __nv_bfloat16 lB = __float2bfloat16(vB - __bfloat162float(hB));
        hi[i >> 1] = (uint)__bfloat16_as_ushort(hA) | ((uint)__bfloat16_as_ushort(hB) << 16);
        lo[i >> 1] = (uint)__bfloat16_as_ushort(lA) | ((uint)__bfloat16_as_ushort(lB) << 16);
    }
    char* Ah = smem + bufoff + px * 80 + kg * 8;
    *(uint2*)(Ah)          = make_uint2(hi[0], hi[1]);
    *(uint2*)(Ah + ABYTES) = make_uint2(lo[0], lo[1]);
}

__global__ __launch_bounds__(512, 2) void dcn_main_mma(
    const float* __restrict__ input,
    const float* __restrict__ b_dcn,
    float* __restrict__ out) {
    extern __shared__ char smem[];
    const int tid  = threadIdx.x;
    const int wid  = tid >> 5;
    const int lane = tid & 31;
    const int b    = blockIdx.y;
    const int y    = blockIdx.x;          // one image row per CTA

    const uint sbase = smem_u32(smem);
    float4*  s_wm4 = (float4*)(smem + SM_WM);
    ushort4* s_im4 = (ushort4*)(smem + SM_IM);
    const size_t GSTR = (size_t)BB * KKN * HW * HW;

    // Phase 1: bilinear metadata for 1 row x 9 taps x 64 px.
    for (int j = tid; j < 576; j += 512) {
        int k   = j >> 6;
        int px  = j & 63;
        const float* p = g_om + (((size_t)b * KKN + k) * HW + y) * HW + px;
        float dy = p[0];
        float dx = p[GSTR];
        float m  = p[2 * GSTR];
        int ki = k / 3, kj = k - ki * 3;
        float py  = (float)(y - 1 + ki) + dy;
        float pxx = (float)(px - 1 + kj) + dx;
        float y0f = floorf(py), x0f = floorf(pxx);
        float ly = py - y0f, lx = pxx - x0f;
        int yy0 = (int)y0f, xx0 = (int)x0f;
        int yy1 = yy0 + 1,  xx1 = xx0 + 1;
        bool vy0 = (yy0 >= 0) && (yy0 < HW);
        bool vy1 = (yy1 >= 0) && (yy1 < HW);
        bool vx0 = (xx0 >= 0) && (xx0 < HW);
        bool vx1 = (xx1 >= 0) && (xx1 < HW);
        int cy0 = min(max(yy0, 0), HW - 1), cy1 = min(max(yy1, 0), HW - 1);
        int cx0 = min(max(xx0, 0), HW - 1), cx1 = min(max(xx1, 0), HW - 1);
        float w00 = (vy0 && vx0) ? (1.f - ly) * (1.f - lx) * m : 0.f;
        float w01 = (vy0 && vx1) ? (1.f - ly) * lx * m : 0.f;
        float w10 = (vy1 && vx0) ? ly * (1.f - lx) * m : 0.f;
        float w11 = (vy1 && vx1) ? ly * lx * m : 0.f;
        s_wm4[j] = make_float4(w00, w01, w10, w11);
        s_im4[j] = make_ushort4((ushort)(cy0 * HW + cx0), (ushort)(cy0 * HW + cx1),
                                (ushort)(cy1 * HW + cx0), (ushort)(cy1 * HW + cx1));
    }
    __syncthreads();

    // Warp tiling: 4 warps along M (16 px each), 4 along N (64 oc each).
    const int mwarp = (wid & 3) * 16;
    const int nwarp = (wid >> 2) * 64;
    const uint aLane = (uint)((mwarp + (lane & 15)) * 80 + ((lane >> 4) & 1) * 16);
    const uint bLane = (uint)((nwarp + (lane & 7) + ((lane >> 4) & 1) * 8) * 80
                              + ((lane >> 3) & 1) * 16);

    float acc[8][4];
#pragma unroll
    for (int nt = 0; nt < 8; ++nt)
#pragma unroll
        for (int q = 0; q < 4; ++q) acc[nt][q] = 0.f;

    stage_chunk(smem, SM_BUF, 0, b, tid, s_wm4, s_im4, input);
    __syncthreads();

#pragma unroll 1
    for (int t = 0; t < CHUNKS; ++t) {
        const int s = t & 1;
        if (t + 1 < CHUNKS)
            stage_chunk(smem, SM_BUF + (s ^ 1) * STGB, t + 1, b, tid, s_wm4, s_im4, input);

        const uint aBase = sbase + SM_BUF + s * STGB + aLane;
        const uint bBase = sbase + SM_BUF + s * STGB + 2 * ABYTES + bLane;
#pragma unroll
        for (int ks = 0; ks < 2; ++ks) {
            uint ah[4], al[4];
            LDM_X4(ah, aBase + ks * 32);
            LDM_X4(al, aBase + ks * 32 + ABYTES);
#pragma unroll
            for (int g = 0; g < 4; ++g) {
                uint bh[4], bl[4];
                uint ba = bBase + g * (16 * 80) + ks * 32;
                LDM_X4(bh, ba);
                LDM_X4(bl, ba + BBYTES);
                MMA16816(acc[2 * g],     ah, bh);
                MMA16816(acc[2 * g],     ah, bl);
                MMA16816(acc[2 * g],     al, bh);
                MMA16816(acc[2 * g + 1], ah, bh + 2);
                MMA16816(acc[2 * g + 1], ah, bl + 2);
                MMA16816(acc[2 * g + 1], al, bh + 2);
            }
        }
        __syncthreads();
    }

    // Epilogue: register accumulators -> gmem, bias added.
    const int tq = lane >> 2, tr = lane & 3;
#pragma unroll
    for (int nt = 0; nt < 8; ++nt) {
        int oc = nwarp + nt * 8 + tr * 2;
        float bz0 = __ldg(b_dcn + oc);
        float bz1 = __ldg(b_dcn + oc + 1);
        int x = mwarp + tq;
        float* orow = out + ((size_t)(b * COUT + oc)) * (HW * HW) + y * HW + x;
        orow[0]           = acc[nt][0] + bz0;
        orow[HW * HW]     = acc[nt][1] + bz1;
        orow[8]           = acc[nt][2] + bz0;
        orow[HW * HW + 8] = acc[nt][3] + bz1;
    }
}

// ---------------------------------------------------------------------------
extern "C" void kernel_launch(void* const* d_in, const int* in_sizes, int n_in,
                              void* d_out, int out_size) {
    const float* input = (const float*)d_in[0];
    const float* w_om  = (const float*)d_in[1];
    const float* b_om  = (const float*)d_in[2];
    const float* w_dcn = (const float*)d_in[3];
    const float* b_dcn = (const float*)d_in[4];
    float* out = (float*)d_out;

    cudaFuncSetAttribute(om2_kernel,
                         cudaFuncAttributeMaxDynamicSharedMemorySize, SM2_TOTAL);
    cudaFuncSetAttribute(dcn_main_mma,
                         cudaFuncAttributeMaxDynamicSharedMemorySize, SM_TOTAL);

    // DEPENDENCY ORDER: prep_wo before om2; prep_w before main.
    prep_wo_kernel<<<(CHUNKS * 32 * 32) / 256, 256>>>(w_om);
    om2_kernel<<<dim3(HW / 4, BB), 512, SM2_TOTAL>>>(input, b_om);
    prep_w_kernel<<<(CHUNKS * COUT * 32) / 256, 256>>>(w_dcn);
    dcn_main_mma<<<dim3(HW, BB), 512, SM_TOTAL>>>(input, b_dcn, out);
}

// round 16
// speedup vs baseline: 1.0053x; 1.0053x over previous
#include <cuda_runtime.h>
#include <cuda_bf16.h>
#include <cstdint>

// DCNv2 forward. BOTH convs on tensor cores (mma.sync m16n8k16 bf16 hi/lo
// split). R14: main kernel smem cut to 99840 B (B tiles = 64B XOR-swizzled
// rows, staged by cp.async) so 2 CTAs/SM actually fit (occ 25% -> 50%).

typedef unsigned int uint;
typedef unsigned short ushort;

#define BB     8
#define CIN    256
#define COUT   256
#define HW     64
#define KKN    9
#define KTOT   2304
#define CHUNKS 72            // K chunks of 32 (2 k16 steps each)

// ---------------- device scratch (static: allocation-free) ----------------
__device__ float g_om[3 * BB * KKN * HW * HW];
__device__ __align__(16) __nv_bfloat16 g_wbh[CHUNKS * COUT * 32];
__device__ __align__(16) __nv_bfloat16 g_wbl[CHUNKS * COUT * 32];
__device__ __align__(16) __nv_bfloat16 g_wobh[CHUNKS * 32 * 32];
__device__ __align__(16) __nv_bfloat16 g_wobl[CHUNKS * 32 * 32];

__device__ __forceinline__ uint smem_u32(const void* p) {
    uint a;
    asm("{ .reg .u64 t; cvta.to.shared.u64 t, %1; cvt.u32.u64 %0, t; }"
        : "=r"(a) : "l"(p));
    return a;
}

#define LDM_X4(r, addr) \
    asm volatile("ldmatrix.sync.aligned.m8n8.x4.shared.b16 {%0,%1,%2,%3}, [%4];" \
        : "=r"((r)[0]), "=r"((r)[1]), "=r"((r)[2]), "=r"((r)[3]) : "r"(addr))

#define MMA16816(d, a, b) \
    asm volatile("mma.sync.aligned.m16n8k16.row.col.f32.bf16.bf16.f32 " \
        "{%0,%1,%2,%3},{%4,%5,%6,%7},{%8,%9},{%0,%1,%2,%3};" \
        : "+f"((d)[0]), "+f"((d)[1]), "+f"((d)[2]), "+f"((d)[3]) \
        : "r"((a)[0]), "r"((a)[1]), "r"((a)[2]), "r"((a)[3]), \
          "r"((b)[0]), "r"((b)[1]))

#define CP_ASYNC16(dst, src) \
    asm volatile("cp.async.cg.shared.global [%0], [%1], 16;" \
        :: "r"(dst), "l"(src))
#define CP_COMMIT() asm volatile("cp.async.commit_group;" ::: "memory")
#define CP_WAIT0()  asm volatile("cp.async.wait_group 0;" ::: "memory")

// ---------------------------------------------------------------------------
// Kernel P1: dense bf16-split main weights, chunk-major [t][oc][32].
// ---------------------------------------------------------------------------
__global__ void prep_w_kernel(const float* __restrict__ w_dcn) {
    int i = blockIdx.x * 256 + threadIdx.x;
    int kkl = i & 31;
    int oc  = (i >> 5) & 255;
    int t   = i >> 13;
    int kk  = t * 32 + kkl;
    int c   = kk / 9;
    int k   = kk - c * 9;
    float w = w_dcn[(oc * CIN + c) * KKN + k];
    __nv_bfloat16 h = __float2bfloat16(w);
    g_wbh[i] = h;
    g_wbl[i] = __float2bfloat16(w - __bfloat162float(h));
}

// ---------------------------------------------------------------------------
// Kernel P2: om weights, padded to 32 oc, chunk-major [t][oc32][32].
// ---------------------------------------------------------------------------
__global__ void prep_wo_kernel(const float* __restrict__ w_om) {
    int i = blockIdx.x * 256 + threadIdx.x;
    int kkl = i & 31;
    int oc  = (i >> 5) & 31;
    int t   = i >> 10;
    int kk  = t * 32 + kkl;
    int c   = kk / 9;
    int k   = kk - c * 9;
    float w = (oc < 27) ? w_om[(oc * CIN + c) * KKN + k] : 0.f;
    __nv_bfloat16 h = __float2bfloat16(w);
    g_wobh[i] = h;
    g_wobl[i] = __float2bfloat16(w - __bfloat162float(h));
}

// ---------------------------------------------------------------------------
// Kernel A (om2): offset/mask conv as mma GEMM (verified R12 form).
// ---------------------------------------------------------------------------
#define A2BYTES 20480
#define B2BYTES 2560
#define STGB2   46080
#define SM2_TOTAL (2 * STGB2)

__device__ __forceinline__ void stage_om(
    char* smem, int bufoff, int t, int b, int y0, int tid,
    const float* __restrict__ input) {
    if (tid < 64) {
        int oc = tid & 31;
        const __nv_bfloat16* srcp = (tid < 32) ? g_wobh : g_wobl;
        const uint4* src = (const uint4*)(srcp + ((size_t)t * 32 + oc) * 32);
        char* dst = smem + bufoff + 2 * A2BYTES + ((tid >= 32) ? B2BYTES : 0) + oc * 80;
#pragma unroll
        for (int q = 0; q < 4; ++q)
            *(uint4*)(dst + q * 16) = src[q];
    }
    const int px = tid & 255;
    const int kg = tid >> 8;
    const int x  = px & 63;
    const int y  = y0 + (px >> 6);
    const int kks = t * 32 + kg * 16;
    int c = kks / 9;
    int k = kks - c * 9;
    const float* pl = input + (((size_t)b * CIN + c) << 12);
    uint hi[8], lo[8];
#pragma unroll
    for (int i = 0; i < 16; ++i) {
        int ki = k / 3, kj = k - ki * 3;
        int yy = y - 1 + ki, xx = x - 1 + kj;
        float v = 0.f;
        if (yy >= 0 && yy < HW && xx >= 0 && xx < HW)
            v = __ldg(pl + yy * HW + xx);
        __nv_bfloat16 h = __float2bfloat16(v);
        __nv_bfloat16 l = __float2bfloat16(v - __bfloat162float(h));
        uint hu = (uint)__bfloat16_as_ushort(h);
        uint lu = (uint)__bfloat16_as_ushort(l);
        if (i & 1) { hi[i >> 1] |= hu << 16; lo[i >> 1] |= lu << 16; }
        else       { hi[i >> 1]  = hu;       lo[i >> 1]  = lu; }
        if (++k == 9) { k = 0; pl += HW * HW; }
    }
    char* Ah = smem + bufoff + px * 80 + kg * 32;
#pragma unroll
    for (int q = 0; q < 2; ++q) {
        *(uint4*)(Ah + q * 16)           = make_uint4(hi[q*4], hi[q*4+1], hi[q*4+2], hi[q*4+3]);
        *(uint4*)(Ah + A2BYTES + q * 16) = make_uint4(lo[q*4], lo[q*4+1], lo[q*4+2], lo[q*4+3]);
    }
}

__global__ __launch_bounds__(512, 1) void om2_kernel(
    const float* __restrict__ input,
    const float* __restrict__ b_om) {
    extern __shared__ char smem[];
    const int tid  = threadIdx.x;
    const int wid  = tid >> 5;
    const int lane = tid & 31;
    const int y0   = blockIdx.x * 4;
    const int b    = blockIdx.y;
    const uint sbase = smem_u32(smem);

    const int mwarp = wid * 16;
    const uint aLane = (uint)((mwarp + (lane & 15)) * 80 + ((lane >> 4) & 1) * 16);
    const uint bLane = (uint)(((lane & 7) + ((lane >> 4) & 1) * 8) * 80
                              + ((lane >> 3) & 1) * 16);

    float acc[4][4];
#pragma unroll
    for (int nt = 0; nt < 4; ++nt)
#pragma unroll
        for (int q = 0; q < 4; ++q) acc[nt][q] = 0.f;

    stage_om(smem, 0, 0, b, y0, tid, input);
    __syncthreads();

#pragma unroll 1
    for (int t = 0; t < CHUNKS; ++t) {
        const int s = t & 1;
        if (t + 1 < CHUNKS)
            stage_om(smem, (s ^ 1) * STGB2, t + 1, b, y0, tid, input);

        const uint aBase = sbase + s * STGB2 + aLane;
        const uint bBase = sbase + s * STGB2 + 2 * A2BYTES + bLane;
#pragma unroll
        for (int ks = 0; ks < 2; ++ks) {
            uint ah[4], al[4];
            LDM_X4(ah, aBase + ks * 32);
            LDM_X4(al, aBase + ks * 32 + A2BYTES);
#pragma unroll
            for (int g = 0; g < 2; ++g) {
                uint bh[4], bl[4];
                uint ba = bBase + g * (16 * 80) + ks * 32;
                LDM_X4(bh, ba);
                LDM_X4(bl, ba + B2BYTES);
                MMA16816(acc[2 * g],     ah, bh);
                MMA16816(acc[2 * g],     ah, bl);
                MMA16816(acc[2 * g],     al, bh);
                MMA16816(acc[2 * g + 1], ah, bh + 2);
                MMA16816(acc[2 * g + 1], ah, bl + 2);
                MMA16816(acc[2 * g + 1], al, bh + 2);
            }
        }
        __syncthreads();
    }

    const int tq = lane >> 2, tr = lane & 3;
#pragma unroll
    for (int nt = 0; nt < 4; ++nt) {
#pragma unroll
        for (int q = 0; q < 4; ++q) {
            int oc = nt * 8 + tr * 2 + (q & 1);
            if (oc >= 27) continue;
            int px = mwarp + tq + ((q >> 1) ? 8 : 0);
            int y  = y0 + (px >> 6);
            int x  = px & 63;
            float v = acc[nt][q] + __ldg(b_om + oc);
            int grp = oc / 9;
            int k   = oc - grp * 9;
            if (grp == 2) v = 1.f / (1.f + expf(-v));
            g_om[(((size_t)grp * BB + b) * KKN + k) * (HW * HW) + y * HW + x] = v;
        }
    }
}

// ---------------------------------------------------------------------------
// Kernel B: fused bilinear sampling + mma.sync GEMM.
// R14: CTA = 1 row (64 px) x 256 oc, 512 threads, warp tile 16x64.
// A: 80B rows (verified). B: 64B XOR-swizzled rows staged via cp.async.
// smem 99840 B -> 2 CTAs/SM.
// ---------------------------------------------------------------------------
#define ABYTES 5120             // 64 rows * 80 B (one A split)
#define BSPL   16384            // 256 rows * 64 B (one B split)
#define STGB   (2 * ABYTES + 2 * BSPL)   // 43008
#define SM_WM  0                // float4[576]
#define SM_IM  9216             // ushort4[576]
#define SM_BUF 13824
#define SM_TOTAL (SM_BUF + 2 * STGB)   // 99840

// B row swizzle key: invariant under row+16 (bits 0..3 preserved).
#define BKEY(r) ((((r) ^ ((r) >> 2))) & 3)

__device__ __forceinline__ void stage_B_async(
    uint sbase, int bufoff, int t, int tid) {
    const int oc    = tid & 255;
    const int split = tid >> 8;
    const __nv_bfloat16* srcp = split ? g_wbl : g_wbh;
    const char* src = (const char*)(srcp + ((size_t)t * COUT + oc) * 32);
    const uint dstb = sbase + bufoff + 2 * ABYTES + split * BSPL + oc * 64;
    const uint key  = BKEY(oc);
#pragma unroll
    for (int q = 0; q < 4; ++q)
        CP_ASYNC16(dstb + ((q ^ key) << 4), src + q * 16);
}

__device__ __forceinline__ void stage_A(
    char* smem, int bufoff, int t, int b, int tid,
    const float4* s_wm4, const ushort4* s_im4,
    const float* __restrict__ input) {
    const int px = tid & 63;
    const int kg = tid >> 6;              // 0..7
    const int kks = t * 32 + kg * 4;
    int c = kks / 9;
    int k = kks - c * 9;
    const float* pl = input + (((size_t)b * CIN + c) << 12);
    uint hi[2], lo[2];
#pragma unroll
    for (int i = 0; i < 4; i += 2) {
        int mA = px + k * 64;
        const float* plA = pl;
        float4  wA = s_wm4[mA];
        ushort4 iA = s_im4[mA];
        if (++k == 9) { k = 0; pl += HW * HW; }
        int mB = px + k * 64;
        const float* plB = pl;
        float4  wB = s_wm4[mB];
        ushort4 iB = s_im4[mB];
        if (++k == 9) { k = 0; pl += HW * HW; }
        float a0 = __ldg(plA + iA.x), a1 = __ldg(plA + iA.y);
        float a2 = __ldg(plA + iA.z), a3 = __ldg(plA + iA.w);
        float b0 = __ldg(plB + iB.x), b1 = __ldg(plB + iB.y);
        float b2 = __ldg(plB + iB.z), b3 = __ldg(plB + iB.w);
        float vA = wA.x * a0 + wA.y * a1 + wA.z * a2 + wA.w * a3;
        float vB = wB.x * b0 + wB.y * b1 + wB.z * b2 + wB.w * b3;
        __nv_bfloat16 hA = __float2bfloat16(vA);
        __nv_bfloat16 lA = __float2bfloat16(vA - __bfloat162float(hA));
        __nv_bfloat16 hB = __float2bfloat16(vB);
        __nv_bfloat16 lB = __float2bfloat16(vB - __bfloat162float(hB));
        hi[i >> 1] = (uint)__bfloat16_as_ushort(hA) | ((uint)__bfloat16_as_ushort(hB) << 16);
        lo[i >> 1] = (uint)__bfloat16_as_ushort(lA) | ((uint)__bfloat16_as_ushort(lB) << 16);
    }
    char* Ah = smem + bufoff + px * 80 + kg * 8;
    *(uint2*)(Ah)          = make_uint2(hi[0], hi[1]);
    *(uint2*)(Ah + ABYTES) = make_uint2(lo[0], lo[1]);
}

__global__ __launch_bounds__(512, 2) void dcn_main_mma(
    const float* __restrict__ input,
    const float* __restrict__ b_dcn,
    float* __restrict__ out) {
    extern __shared__ char smem[];
    const int tid  = threadIdx.x;
    const int wid  = tid >> 5;
    const int lane = tid & 31;
    const int b    = blockIdx.y;
    const int y    = blockIdx.x;          // one image row per CTA

    const uint sbase = smem_u32(smem);
    float4*  s_wm4 = (float4*)(smem + SM_WM);
    ushort4* s_im4 = (ushort4*)(smem + SM_IM);
    const size_t GSTR = (size_t)BB * KKN * HW * HW;

    // Phase 1: bilinear metadata for 1 row x 9 taps x 64 px.
    for (int j = tid; j < 576; j += 512) {
        int k   = j >> 6;
        int px  = j & 63;
        const float* p = g_om + (((size_t)b * KKN + k) * HW + y) * HW + px;
        float dy = p[0];
        float dx = p[GSTR];
        float m  = p[2 * GSTR];
        int ki = k / 3, kj = k - ki * 3;
        float py  = (float)(y - 1 + ki) + dy;
        float pxx = (float)(px - 1 + kj) + dx;
        float y0f = floorf(py), x0f = floorf(pxx);
        float ly = py - y0f, lx = pxx - x0f;
        int yy0 = (int)y0f, xx0 = (int)x0f;
        int yy1 = yy0 + 1,  xx1 = xx0 + 1;
        bool vy0 = (yy0 >= 0) && (yy0 < HW);
        bool vy1 = (yy1 >= 0) && (yy1 < HW);
        bool vx0 = (xx0 >= 0) && (xx0 < HW);
        bool vx1 = (xx1 >= 0) && (xx1 < HW);
        int cy0 = min(max(yy0, 0), HW - 1), cy1 = min(max(yy1, 0), HW - 1);
        int cx0 = min(max(xx0, 0), HW - 1), cx1 = min(max(xx1, 0), HW - 1);
        float w00 = (vy0 && vx0) ? (1.f - ly) * (1.f - lx) * m : 0.f;
        float w01 = (vy0 && vx1) ? (1.f - ly) * lx * m : 0.f;
        float w10 = (vy1 && vx0) ? ly * (1.f - lx) * m : 0.f;
        float w11 = (vy1 && vx1) ? ly * lx * m : 0.f;
        s_wm4[j] = make_float4(w00, w01, w10, w11);
        s_im4[j] = make_ushort4((ushort)(cy0 * HW + cx0), (ushort)(cy0 * HW + cx1),
                                (ushort)(cy1 * HW + cx0), (ushort)(cy1 * HW + cx1));
    }
    __syncthreads();

    // Warp tiling: 4 warps along M (16 px each), 4 along N (64 oc each).
    const int mwarp = (wid & 3) * 16;
    const int nwarp = (wid >> 2) * 64;
    const uint aLane = (uint)((mwarp + (lane & 15)) * 80 + ((lane >> 4) & 1) * 16);
    // B lane: row within 256, 64B swizzled rows.
    const int  bRow  = nwarp + (lane & 7) + ((lane >> 4) & 1) * 8;
    const uint bSel  = (lane >> 3) & 1;
    const uint bKey  = BKEY(bRow);
    const uint bRB   = (uint)(bRow * 64);
    const uint bC0   = ((bSel ^ bKey) << 4);           // ks=0 chunk offset
    const uint bC1   = (((2u | bSel) ^ bKey) << 4);    // ks=1 chunk offset

    float acc[8][4];
#pragma unroll
    for (int nt = 0; nt < 8; ++nt)
#pragma unroll
        for (int q = 0; q < 4; ++q) acc[nt][q] = 0.f;

    stage_B_async(sbase, SM_BUF, 0, tid);
    CP_COMMIT();
    stage_A(smem, SM_BUF, 0, b, tid, s_wm4, s_im4, input);
    CP_WAIT0();
    __syncthreads();

#pragma unroll 1
    for (int t = 0; t < CHUNKS; ++t) {
        const int s = t & 1;
        if (t + 1 < CHUNKS) {
            stage_B_async(sbase, SM_BUF + (s ^ 1) * STGB, t + 1, tid);
            CP_COMMIT();
            stage_A(smem, SM_BUF + (s ^ 1) * STGB, t + 1, b, tid, s_wm4, s_im4, input);
        }

        const uint aBase = sbase + SM_BUF + s * STGB + aLane;
        const uint bBase = sbase + SM_BUF + s * STGB + 2 * ABYTES + bRB;
#pragma unroll
        for (int ks = 0; ks < 2; ++ks) {
            uint ah[4], al[4];
            LDM_X4(ah, aBase + ks * 32);
            LDM_X4(al, aBase + ks * 32 + ABYTES);
            const uint bco = ks ? bC1 : bC0;
#pragma unroll
            for (int g = 0; g < 4; ++g) {
                uint bh[4], bl[4];
                uint ba = bBase + g * 1024 + bco;
                LDM_X4(bh, ba);
                LDM_X4(bl, ba + BSPL);
                MMA16816(acc[2 * g],     ah, bh);
                MMA16816(acc[2 * g],     ah, bl);
                MMA16816(acc[2 * g],     al, bh);
                MMA16816(acc[2 * g + 1], ah, bh + 2);
                MMA16816(acc[2 * g + 1], ah, bl + 2);
                MMA16816(acc[2 * g + 1], al, bh + 2);
            }
        }
        CP_WAIT0();
        __syncthreads();
    }

    // Epilogue: register accumulators -> gmem, bias added.
    const int tq = lane >> 2, tr = lane & 3;
#pragma unroll
    for (int nt = 0; nt < 8; ++nt) {
        int oc = nwarp + nt * 8 + tr * 2;
        float bz0 = __ldg(b_dcn + oc);
        float bz1 = __ldg(b_dcn + oc + 1);
        int x = mwarp + tq;
        float* orow = out + ((size_t)(b * COUT + oc)) * (HW * HW) + y * HW + x;
        orow[0]           = acc[nt][0] + bz0;
        orow[HW * HW]     = acc[nt][1] + bz1;
        orow[8]           = acc[nt][2] + bz0;
        orow[HW * HW + 8] = acc[nt][3] + bz1;
    }
}

// ---------------------------------------------------------------------------
extern "C" void kernel_launch(void* const* d_in, const int* in_sizes, int n_in,
                              void* d_out, int out_size) {
    const float* input = (const float*)d_in[0];
    const float* w_om  = (const float*)d_in[1];
    const float* b_om  = (const float*)d_in[2];
    const float* w_dcn = (const float*)d_in[3];
    const float* b_dcn = (const float*)d_in[4];
    float* out = (float*)d_out;

    cudaFuncSetAttribute(om2_kernel,
                         cudaFuncAttributeMaxDynamicSharedMemorySize, SM2_TOTAL);
    cudaFuncSetAttribute(dcn_main_mma,
                         cudaFuncAttributeMaxDynamicSharedMemorySize, SM_TOTAL);

    // DEPENDENCY ORDER: prep_wo before om2; prep_w before main.
    prep_wo_kernel<<<(CHUNKS * 32 * 32) / 256, 256>>>(w_om);
    om2_kernel<<<dim3(HW / 4, BB), 512, SM2_TOTAL>>>(input, b_om);
    prep_w_kernel<<<(CHUNKS * COUT * 32) / 256, 256>>>(w_dcn);
    dcn_main_mma<<<dim3(HW, BB), 512, SM_TOTAL>>>(input, b_dcn, out);
}